// round 13
// baseline (speedup 1.0000x reference)
#include <cuda_runtime.h>
#include <cuda_fp16.h>
#include <math.h>
#include <float.h>
#include <stdint.h>

#define BATCH 2
#define SEQ   2048
#define TOK   (BATCH*SEQ)        // 4096
#define EMB   1024
#define HEADS 16
#define HD    64
#define FF    4096
#define QKV_LD 3072

// ==================== helpers ====================
__device__ __forceinline__ uint32_t smem_u32(const void* p) {
    uint32_t a;
    asm("{ .reg .u64 t; cvta.to.shared.u64 t, %1; cvt.u32.u64 %0, t; }" : "=r"(a) : "l"(p));
    return a;
}
#define SWZ(x) ((x) ^ (((x) >> 3) & 0x70))

__device__ __forceinline__ void cp_async16(uint32_t saddr, const void* gptr) {
    asm volatile("cp.async.cg.shared.global [%0], [%1], 16;" :: "r"(saddr), "l"(gptr));
}
#define CP_COMMIT() asm volatile("cp.async.commit_group;" ::: "memory")
#define CP_WAIT2()  asm volatile("cp.async.wait_group 2;" ::: "memory")
#define CP_WAIT1()  asm volatile("cp.async.wait_group 1;" ::: "memory")
#define CP_WAIT0()  asm volatile("cp.async.wait_group 0;" ::: "memory")

__device__ __forceinline__ void ldsm_x4(uint32_t addr, uint32_t r[4]) {
    asm volatile("ldmatrix.sync.aligned.m8n8.x4.shared.b16 {%0,%1,%2,%3}, [%4];"
                 : "=r"(r[0]), "=r"(r[1]), "=r"(r[2]), "=r"(r[3]) : "r"(addr));
}
__device__ __forceinline__ void ldsm_x4t(uint32_t addr, uint32_t r[4]) {
    asm volatile("ldmatrix.sync.aligned.m8n8.x4.trans.shared.b16 {%0,%1,%2,%3}, [%4];"
                 : "=r"(r[0]), "=r"(r[1]), "=r"(r[2]), "=r"(r[3]) : "r"(addr));
}
__device__ __forceinline__ void mma_f16(float c[4], const uint32_t a[4], const uint32_t b0, const uint32_t b1) {
    asm volatile("mma.sync.aligned.m16n8k16.row.col.f32.f16.f16.f32 "
                 "{%0,%1,%2,%3}, {%4,%5,%6,%7}, {%8,%9}, {%0,%1,%2,%3};"
                 : "+f"(c[0]), "+f"(c[1]), "+f"(c[2]), "+f"(c[3])
                 : "r"(a[0]), "r"(a[1]), "r"(a[2]), "r"(a[3]), "r"(b0), "r"(b1));
}
__device__ __forceinline__ uint32_t h2(float a, float b) {
    __half2 t = __floats2half2_rn(a, b);
    return *(uint32_t*)&t;
}
__device__ __forceinline__ uint32_t ex2_f16x2(uint32_t x) {
    uint32_t r;
    asm("ex2.approx.f16x2 %0, %1;" : "=r"(r) : "r"(x));
    return r;
}
__device__ __forceinline__ float ex2f(float x) {
    float r;
    asm("ex2.approx.f32 %0, %1;" : "=f"(r) : "f"(x));
    return r;
}
__device__ __forceinline__ float tanh_ap(float x) {
    float r;
    asm("tanh.approx.f32 %0, %1;" : "=f"(r) : "f"(x));
    return r;
}
__device__ __forceinline__ float gelu_t(float v) {
    float t = tanh_ap(0.7978845608028654f * (v + 0.044715f * v * v * v));
    return 0.5f * v * (1.0f + t);
}
#define ONES_H2 0x3C003C00u   // (1.0h, 1.0h)

// ==================== scratch (device globals) ====================
__device__ __half g_h[TOK*EMB];
__device__ __half g_qkv[TOK*QKV_LD];
__device__ __half g_ctx[TOK*EMB];
__device__ float  g_x1[TOK*EMB];
__device__ __half g_mid[TOK*FF];
__device__ __half g_wqkv[QKV_LD*EMB];   // [N=3072][K=1024]
__device__ __half g_wo[EMB*EMB];
__device__ __half g_w1[EMB*FF];         // [N=FF][K=EMB]
__device__ __half g_w2[FF*EMB];         // [N=EMB][K=FF]

// ==================== batched square transpose ====================
__global__ __launch_bounds__(256) void transpose4_kernel(
    const float* __restrict__ Wq, const float* __restrict__ Wk,
    const float* __restrict__ Wv, const float* __restrict__ Wo,
    __half* __restrict__ Tq, __half* __restrict__ Tk,
    __half* __restrict__ Tv, __half* __restrict__ To)
{
    __shared__ float t[32][33];
    const float* W = (blockIdx.z == 0) ? Wq : (blockIdx.z == 1) ? Wk : (blockIdx.z == 2) ? Wv : Wo;
    __half*      T = (blockIdx.z == 0) ? Tq : (blockIdx.z == 1) ? Tk : (blockIdx.z == 2) ? Tv : To;
    int tx = threadIdx.x & 31, ty = threadIdx.x >> 5;
    int k0 = blockIdx.y * 32, n0 = blockIdx.x * 32;
    #pragma unroll
    for (int i = 0; i < 4; i++)
        t[ty + i*8][tx] = W[(size_t)(k0 + ty + i*8) * EMB + n0 + tx];
    __syncthreads();
    #pragma unroll
    for (int i = 0; i < 4; i++)
        T[(size_t)(n0 + ty + i*8) * EMB + k0 + tx] = __float2half_rn(t[tx][ty + i*8]);
}

// ==================== rect transpose ====================
__global__ __launch_bounds__(256) void transpose_half_kernel(
    const float* __restrict__ W, __half* __restrict__ T, int K, int N)
{
    __shared__ float t[32][33];
    int tx = threadIdx.x & 31, ty = threadIdx.x >> 5;
    int k0 = blockIdx.y * 32, n0 = blockIdx.x * 32;
    #pragma unroll
    for (int i = 0; i < 4; i++)
        t[ty + i*8][tx] = W[(size_t)(k0 + ty + i*8) * N + n0 + tx];
    __syncthreads();
    #pragma unroll
    for (int i = 0; i < 4; i++)
        T[(size_t)(n0 + ty + i*8) * K + k0 + tx] = __float2half_rn(t[tx][ty + i*8]);
}

// ==================== LayerNorm -> fp16, warp-per-row, 2 rows / 64-thread CTA ====================
__global__ __launch_bounds__(64) void ln_half_kernel(
    const float* __restrict__ X, const float* __restrict__ scale,
    const float* __restrict__ shift, __half* __restrict__ Y)
{
    const int lane = threadIdx.x & 31;
    const int row  = blockIdx.x * 2 + (threadIdx.x >> 5);
    const float* x = X + (size_t)row * EMB;

    float4 v[8];
    float s = 0.0f;
    #pragma unroll
    for (int i = 0; i < 8; i++) {
        v[i] = *(const float4*)(x + (i * 32 + lane) * 4);
        s += v[i].x + v[i].y + v[i].z + v[i].w;
    }
    #pragma unroll
    for (int o = 16; o > 0; o >>= 1) s += __shfl_xor_sync(0xffffffffu, s, o);
    float mean = s * (1.0f / EMB);

    float sq = 0.0f;
    #pragma unroll
    for (int i = 0; i < 8; i++) {
        v[i].x -= mean; v[i].y -= mean; v[i].z -= mean; v[i].w -= mean;
        sq += v[i].x*v[i].x + v[i].y*v[i].y + v[i].z*v[i].z + v[i].w*v[i].w;
    }
    #pragma unroll
    for (int o = 16; o > 0; o >>= 1) sq += __shfl_xor_sync(0xffffffffu, sq, o);
    float rstd = rsqrtf(sq * (1.0f / EMB) + 1e-5f);

    #pragma unroll
    for (int i = 0; i < 8; i++) {
        int c0 = (i * 32 + lane) * 4;
        float4 sc = *(const float4*)(scale + c0);
        float4 sh = *(const float4*)(shift + c0);
        size_t o = (size_t)row * EMB + c0;
        *(uint32_t*)(Y + o)     = h2(sc.x * v[i].x * rstd + sh.x, sc.y * v[i].y * rstd + sh.y);
        *(uint32_t*)(Y + o + 2) = h2(sc.z * v[i].z * rstd + sh.z, sc.w * v[i].w * rstd + sh.w);
    }
}

// ==================== fp16 mma.sync GEMM, 3-stage cp.async, 2 CTAs/SM ====================
// C[M][N] = A[M][K] @ B[N][K]^T. CTA tile MT x 128 (MT = 128 or 64), K-chunk 64.
// EPI: 1 +bias+res -> fp32; 2 +bias GELU -> fp16; 3 plain -> fp16
template<int EPI, int MT>
__global__ __launch_bounds__(256, 2)
void gemm_kernel(
    const __half* __restrict__ A, const __half* __restrict__ B,
    const float* __restrict__ bias, const float* __restrict__ res,
    float* __restrict__ C, __half* __restrict__ Ch,
    int M, int N, int K)
{
    constexpr int MI = MT / 32;                 // m16 frags per warp
    constexpr int A_BYTES = MT * 128;
    constexpr int STG = A_BYTES + 16384;

    extern __shared__ char smraw[];
    const uint32_t sbase = smem_u32(smraw);
    const int tid = threadIdx.x;
    const int bm = blockIdx.y, bn = blockIdx.x;

    const int w = tid >> 5, lane = tid & 31;
    const int wm = w & 1, wn = w >> 1;

    const int rowA = (lane & 7) + ((lane >> 3) & 1) * 8;
    const int chA  = (lane >> 4) & 1;
    const int gB   = lane >> 3;
    const int rB   = lane & 7;

    float acc[MI][4][4];
    #pragma unroll
    for (int i = 0; i < MI; i++)
        #pragma unroll
        for (int j = 0; j < 4; j++)
            #pragma unroll
            for (int q = 0; q < 4; q++) acc[i][j][q] = 0.0f;

    const int nchunk = K >> 6;

    auto stage = [&](int s, int c) {
        const uint32_t sb = sbase + s * STG;
        #pragma unroll
        for (int j = 0; j < MT / 32; ++j) {
            int idx = tid + j * 256;
            int r = idx >> 3, seg = idx & 7;
            cp_async16(sb + SWZ((uint32_t)(r * 128 + seg * 16)),
                       A + (size_t)(bm * MT + r) * K + c * 64 + seg * 8);
        }
        #pragma unroll
        for (int j = 0; j < 4; ++j) {
            int idx = tid + j * 256;
            int r = idx >> 3, seg = idx & 7;
            cp_async16(sb + A_BYTES + SWZ((uint32_t)(r * 128 + seg * 16)),
                       B + (size_t)(bn * 128 + r) * K + c * 64 + seg * 8);
        }
    };

    stage(0, 0); CP_COMMIT();
    if (nchunk > 1) { stage(1, 1); CP_COMMIT(); }

    for (int c = 0; c < nchunk; ++c) {
        const int s = c % 3;
        if (c == nchunk - 1) { CP_WAIT0(); } else { CP_WAIT1(); }
        __syncthreads();
        if (c + 2 < nchunk) { stage((c + 2) % 3, c + 2); CP_COMMIT(); }

        const uint32_t sA = sbase + s * STG;
        const uint32_t sB = sA + A_BYTES;

        #pragma unroll
        for (int ks = 0; ks < 4; ++ks) {
            uint32_t ah[MI][4], bh[2][4];
            #pragma unroll
            for (int mi = 0; mi < MI; ++mi) {
                uint32_t off = (uint32_t)((wm * (MT/2) + mi * 16 + rowA) * 128 + (ks * 2 + chA) * 16);
                ldsm_x4(sA + SWZ(off), ah[mi]);
            }
            #pragma unroll
            for (int nb = 0; nb < 2; ++nb) {
                uint32_t off = (uint32_t)((wn * 32 + nb * 16 + (gB >> 1) * 8 + rB) * 128
                                          + ks * 32 + (gB & 1) * 16);
                ldsm_x4(sB + SWZ(off), bh[nb]);
            }
            #pragma unroll
            for (int mi = 0; mi < MI; ++mi)
                #pragma unroll
                for (int ni = 0; ni < 4; ++ni)
                    mma_f16(acc[mi][ni], ah[mi], bh[ni>>1][(ni&1)*2], bh[ni>>1][(ni&1)*2+1]);
        }
    }

    // epilogue
    const int g = lane >> 2, tid4 = lane & 3;
    #pragma unroll
    for (int mi = 0; mi < MI; ++mi) {
        #pragma unroll
        for (int half_ = 0; half_ < 2; ++half_) {
            const size_t row = (size_t)(bm * MT + wm * (MT/2) + mi * 16 + g + half_ * 8);
            #pragma unroll
            for (int ni = 0; ni < 4; ++ni) {
                const int col = bn * 128 + wn * 32 + ni * 8 + tid4 * 2;
                float v0 = acc[mi][ni][half_ * 2 + 0];
                float v1 = acc[mi][ni][half_ * 2 + 1];
                if (EPI == 1) {
                    float2 rv = *(const float2*)(res + row * N + col);
                    float2 bv = *(const float2*)(bias + col);
                    *(float2*)(C + row * N + col) =
                        make_float2(v0 + bv.x + rv.x, v1 + bv.y + rv.y);
                } else if (EPI == 2) {
                    float2 bv = *(const float2*)(bias + col);
                    *(uint32_t*)(Ch + row * N + col) =
                        h2(gelu_t(v0 + bv.x), gelu_t(v1 + bv.y));
                } else {
                    *(uint32_t*)(Ch + row * N + col) = h2(v0, v1);
                }
            }
        }
    }
}

#define GEMM_SMEM_64  (3 * ( 64*128 + 16384))

// ==================== fp16 HMMA causal flash attention, 3-stage KV ====================
#define ATTN_SMEM 65536

__global__ __launch_bounds__(256, 2) void attn_kernel(
    const __half* __restrict__ QKV, __half* __restrict__ O)
{
    extern __shared__ char smraw[];
    const uint32_t sbase = smem_u32(smraw);
    const uint32_t sQ = sbase;

    const int qb = gridDim.x - 1 - blockIdx.x;    // heavy tiles first
    const int h = blockIdx.y, b = blockIdx.z;
    const int tid = threadIdx.x;
    const int w = tid >> 5, lane = tid & 31;
    const int wq0 = w * 16;
    const int g = lane >> 2, c2 = (lane & 3) * 2;
    const size_t rows0 = (size_t)b * SEQ;
    const int hoff = h * HD;

    const int rowA = (lane & 7) + ((lane >> 3) & 1) * 8;
    const int chA  = (lane >> 4) & 1;
    const int gB   = lane >> 3;
    const int rB   = lane & 7;
    const int rowV = lane & 15;
    const int colV = (lane >> 4) * 8;

    for (int i = tid; i < 1024; i += 256) {
        int r = i >> 3, seg = i & 7;
        *(uint4*)(smraw + SWZ((uint32_t)(r * 128 + seg * 16))) =
            *(const uint4*)(QKV + (rows0 + qb * 128 + r) * QKV_LD + hoff + seg * 8);
    }

    auto stageKV = [&](int s, int jb) {
        uint32_t sb = sbase + 16384u + (uint32_t)s * 16384u;
        for (int i = tid; i < 512; i += 256) {
            int r = i >> 3, seg = i & 7;
            const size_t go = (rows0 + jb * 64 + r) * QKV_LD + hoff + seg * 8;
            uint32_t dst = SWZ((uint32_t)(r * 128 + seg * 16));
            cp_async16(sb + dst,         QKV + go + EMB);
            cp_async16(sb + 8192u + dst, QKV + go + 2 * EMB);
        }
    };

    float oacc[8][4];
    #pragma unroll
    for (int i = 0; i < 8; i++)
        #pragma unroll
        for (int q = 0; q < 4; q++) oacc[i][q] = 0.0f;
    float m0 = -1e30f, m1 = -1e30f, l0 = 0.0f, l1 = 0.0f;

    uint32_t qfrag[4][4];

    const int row0 = qb * 128 + wq0 + g;
    const int row1 = row0 + 8;
    const int njb = 2 * qb + 2;
    const float SCL = 0.125f * 1.44269504f;

    stageKV(0, 0); CP_COMMIT();
    if (njb > 1) { stageKV(1, 1); CP_COMMIT(); }

    for (int jb = 0; jb < njb; ++jb) {
        if (jb == njb - 1)      { CP_WAIT0(); }
        else if (jb == njb - 2) { CP_WAIT1(); }
        else                    { CP_WAIT2(); }
        __syncthreads();
        if (jb + 2 < njb) { stageKV((jb + 2) % 3, jb + 2); CP_COMMIT(); }

        if (jb == 0) {
            #pragma unroll
            for (int ks = 0; ks < 4; ++ks)
                ldsm_x4(sQ + SWZ((uint32_t)((wq0 + rowA) * 128 + (ks * 2 + chA) * 16)), qfrag[ks]);
        }

        const uint32_t sK = sbase + 16384u + (uint32_t)(jb % 3) * 16384u;
        const uint32_t sV = sK + 8192u;

        float sacc[8][4];
        #pragma unroll
        for (int i = 0; i < 8; i++)
            #pragma unroll
            for (int q = 0; q < 4; q++) sacc[i][q] = 0.0f;

        #pragma unroll
        for (int ks = 0; ks < 4; ++ks) {
            #pragma unroll
            for (int nb = 0; nb < 4; ++nb) {
                uint32_t bk[4];
                ldsm_x4(sK + SWZ((uint32_t)((nb * 16 + (gB >> 1) * 8 + rB) * 128
                                            + ks * 32 + (gB & 1) * 16)), bk);
                mma_f16(sacc[nb*2+0], qfrag[ks], bk[0], bk[1]);
                mma_f16(sacc[nb*2+1], qfrag[ks], bk[2], bk[3]);
            }
        }

        if (jb >= 2 * qb) {
            const int col0 = jb * 64;
            #pragma unroll
            for (int ni = 0; ni < 8; ++ni) {
                int cg = col0 + ni * 8 + c2;
                sacc[ni][0] = (cg     > row0) ? -1e30f : sacc[ni][0] * SCL;
                sacc[ni][1] = (cg + 1 > row0) ? -1e30f : sacc[ni][1] * SCL;
                sacc[ni][2] = (cg     > row1) ? -1e30f : sacc[ni][2] * SCL;
                sacc[ni][3] = (cg + 1 > row1) ? -1e30f : sacc[ni][3] * SCL;
            }
        } else {
            #pragma unroll
            for (int ni = 0; ni < 8; ++ni) {
                sacc[ni][0] *= SCL; sacc[ni][1] *= SCL;
                sacc[ni][2] *= SCL; sacc[ni][3] *= SCL;
            }
        }

        float rmax0 = -1e30f, rmax1 = -1e30f;
        #pragma unroll
        for (int ni = 0; ni < 8; ++ni) {
            rmax0 = fmaxf(rmax0, fmaxf(sacc[ni][0], sacc[ni][1]));
            rmax1 = fmaxf(rmax1, fmaxf(sacc[ni][2], sacc[ni][3]));
        }
        #pragma unroll
        for (int o = 1; o <= 2; o <<= 1) {
            rmax0 = fmaxf(rmax0, __shfl_xor_sync(0xffffffffu, rmax0, o));
            rmax1 = fmaxf(rmax1, __shfl_xor_sync(0xffffffffu, rmax1, o));
        }
        float mn0 = fmaxf(m0, rmax0), mn1 = fmaxf(m1, rmax1);
        float alpha0 = ex2f(m0 - mn0), alpha1 = ex2f(m1 - mn1);
        m0 = mn0; m1 = mn1;
        #pragma unroll
        for (int ni = 0; ni < 8; ++ni) {
            oacc[ni][0] *= alpha0; oacc[ni][1] *= alpha0;
            oacc[ni][2] *= alpha1; oacc[ni][3] *= alpha1;
        }

        uint32_t pw[8][2];
        #pragma unroll
        for (int ni = 0; ni < 8; ++ni) {
            pw[ni][0] = ex2_f16x2(h2(sacc[ni][0] - mn0, sacc[ni][1] - mn0));
            pw[ni][1] = ex2_f16x2(h2(sacc[ni][2] - mn1, sacc[ni][3] - mn1));
        }

        float rsum[4] = {0.0f, 0.0f, 0.0f, 0.0f};
        #pragma unroll
        for (int kb = 0; kb < 4; ++kb) {
            uint32_t pa[4] = { pw[2*kb][0], pw[2*kb][1], pw[2*kb+1][0], pw[2*kb+1][1] };
            mma_f16(rsum, pa, ONES_H2, ONES_H2);
            #pragma unroll
            for (int nv = 0; nv < 4; ++nv) {
                uint32_t vv[4];
                ldsm_x4t(sV + SWZ((uint32_t)((kb * 16 + rowV) * 128 + (nv * 16 + colV) * 2)), vv);
                mma_f16(oacc[nv*2+0], pa, vv[0], vv[1]);
                mma_f16(oacc[nv*2+1], pa, vv[2], vv[3]);
            }
        }
        l0 = l0 * alpha0 + rsum[0];
        l1 = l1 * alpha1 + rsum[2];
    }

    float il0 = 1.0f / l0, il1 = 1.0f / l1;
    const size_t gr0 = (rows0 + qb * 128 + wq0 + g) * EMB + hoff;
    const size_t gr1 = gr0 + 8 * EMB;
    #pragma unroll
    for (int ni = 0; ni < 8; ++ni) {
        int col = ni * 8 + c2;
        *(uint32_t*)(O + gr0 + col) = h2(oacc[ni][0] * il0, oacc[ni][1] * il0);
        *(uint32_t*)(O + gr1 + col) = h2(oacc[ni][2] * il1, oacc[ni][3] * il1);
    }
}

// ==================== host launch ====================
extern "C" void kernel_launch(void* const* d_in, const int* in_sizes, int n_in,
                              void* d_out, int out_size)
{
    const float* x    = (const float*)d_in[0];
    const float* Wq   = (const float*)d_in[1];
    const float* Wk   = (const float*)d_in[2];
    const float* Wv   = (const float*)d_in[3];
    const float* Wo   = (const float*)d_in[4];
    const float* bo   = (const float*)d_in[5];
    const float* W1   = (const float*)d_in[6];
    const float* b1   = (const float*)d_in[7];
    const float* W2   = (const float*)d_in[8];
    const float* b2   = (const float*)d_in[9];
    const float* ln1s = (const float*)d_in[10];
    const float* ln1b = (const float*)d_in[11];
    const float* ln2s = (const float*)d_in[12];
    const float* ln2b = (const float*)d_in[13];
    float* out = (float*)d_out;

    __half *hh, *qkv, *ctx, *mid, *wqkv, *wo, *w1, *w2;
    float *x1;
    cudaGetSymbolAddress((void**)&hh,   g_h);
    cudaGetSymbolAddress((void**)&qkv,  g_qkv);
    cudaGetSymbolAddress((void**)&ctx,  g_ctx);
    cudaGetSymbolAddress((void**)&x1,   g_x1);
    cudaGetSymbolAddress((void**)&mid,  g_mid);
    cudaGetSymbolAddress((void**)&wqkv, g_wqkv);
    cudaGetSymbolAddress((void**)&wo,   g_wo);
    cudaGetSymbolAddress((void**)&w1,   g_w1);
    cudaGetSymbolAddress((void**)&w2,   g_w2);

    cudaFuncSetAttribute(gemm_kernel<1,64>, cudaFuncAttributeMaxDynamicSharedMemorySize, GEMM_SMEM_64);
    cudaFuncSetAttribute(gemm_kernel<2,64>, cudaFuncAttributeMaxDynamicSharedMemorySize, GEMM_SMEM_64);
    cudaFuncSetAttribute(gemm_kernel<3,64>, cudaFuncAttributeMaxDynamicSharedMemorySize, GEMM_SMEM_64);
    cudaFuncSetAttribute(attn_kernel, cudaFuncAttributeMaxDynamicSharedMemorySize, ATTN_SMEM);

    static cudaStream_t s_side = []{
        cudaStream_t s; cudaStreamCreateWithFlags(&s, cudaStreamNonBlocking); return s; }();
    static cudaEvent_t ev_fork = []{
        cudaEvent_t e; cudaEventCreateWithFlags(&e, cudaEventDisableTiming); return e; }();
    static cudaEvent_t ev_a = []{
        cudaEvent_t e; cudaEventCreateWithFlags(&e, cudaEventDisableTiming); return e; }();
    static cudaEvent_t ev_b = []{
        cudaEvent_t e; cudaEventCreateWithFlags(&e, cudaEventDisableTiming); return e; }();

    // fork: weight transposes on side stream, concurrent with LN1
    cudaEventRecord(ev_fork, 0);
    cudaStreamWaitEvent(s_side, ev_fork, 0);
    transpose4_kernel<<<dim3(EMB/32, EMB/32, 4), 256, 0, s_side>>>(
        Wq, Wk, Wv, Wo, wqkv, wqkv + EMB*EMB, wqkv + 2*EMB*EMB, wo);
    cudaEventRecord(ev_a, s_side);
    transpose_half_kernel<<<dim3(FF/32,  EMB/32), 256, 0, s_side>>>(W1, w1, EMB, FF);
    transpose_half_kernel<<<dim3(EMB/32, FF/32),  256, 0, s_side>>>(W2, w2, FF, EMB);
    cudaEventRecord(ev_b, s_side);

    // main: LN1 concurrent with transpose4
    ln_half_kernel<<<TOK/2, 64>>>(x, ln1s, ln1b, hh);
    cudaStreamWaitEvent(0, ev_a, 0);

    // fused QKV projection -> fp16 (MT=64: 1536 CTAs)
    gemm_kernel<3,64><<<dim3(QKV_LD/128, TOK/64), 256, GEMM_SMEM_64>>>(
        hh, wqkv, nullptr, nullptr, nullptr, qkv, TOK, QKV_LD, EMB);

    // attention -> ctx fp16
    attn_kernel<<<dim3(SEQ/128, HEADS, BATCH), 256, ATTN_SMEM>>>(qkv, ctx);

    // Wo + bias + residual -> x1 (MT=64)
    gemm_kernel<1,64><<<dim3(EMB/128, TOK/64), 256, GEMM_SMEM_64>>>(
        ctx, wo, bo, x, x1, nullptr, TOK, EMB, EMB);

    // LN2 -> h fp16
    ln_half_kernel<<<TOK/2, 64>>>(x1, ln2s, ln2b, hh);

    cudaStreamWaitEvent(0, ev_b, 0);

    // FFN up + GELU -> mid fp16 (MT=64: 2048 CTAs)
    gemm_kernel<2,64><<<dim3(FF/128, TOK/64), 256, GEMM_SMEM_64>>>(
        hh, w1, b1, nullptr, nullptr, mid, TOK, FF, EMB);

    // FFN down + bias + residual -> out (MT=64)
    gemm_kernel<1,64><<<dim3(EMB/128, TOK/64), 256, GEMM_SMEM_64>>>(
        mid, w2, b2, x1, out, nullptr, TOK, EMB, FF);
}

// round 14
// speedup vs baseline: 1.0441x; 1.0441x over previous
#include <cuda_runtime.h>
#include <cuda_fp16.h>
#include <math.h>
#include <float.h>
#include <stdint.h>

#define BATCH 2
#define SEQ   2048
#define TOK   (BATCH*SEQ)        // 4096
#define EMB   1024
#define HEADS 16
#define HD    64
#define FF    4096
#define QKV_LD 3072

// ==================== helpers ====================
__device__ __forceinline__ uint32_t smem_u32(const void* p) {
    uint32_t a;
    asm("{ .reg .u64 t; cvta.to.shared.u64 t, %1; cvt.u32.u64 %0, t; }" : "=r"(a) : "l"(p));
    return a;
}
#define SWZ(x) ((x) ^ (((x) >> 3) & 0x70))

__device__ __forceinline__ void cp_async16(uint32_t saddr, const void* gptr) {
    asm volatile("cp.async.cg.shared.global [%0], [%1], 16;" :: "r"(saddr), "l"(gptr));
}
#define CP_COMMIT() asm volatile("cp.async.commit_group;" ::: "memory")
#define CP_WAIT2()  asm volatile("cp.async.wait_group 2;" ::: "memory")
#define CP_WAIT1()  asm volatile("cp.async.wait_group 1;" ::: "memory")
#define CP_WAIT0()  asm volatile("cp.async.wait_group 0;" ::: "memory")

__device__ __forceinline__ void ldsm_x4(uint32_t addr, uint32_t r[4]) {
    asm volatile("ldmatrix.sync.aligned.m8n8.x4.shared.b16 {%0,%1,%2,%3}, [%4];"
                 : "=r"(r[0]), "=r"(r[1]), "=r"(r[2]), "=r"(r[3]) : "r"(addr));
}
__device__ __forceinline__ void ldsm_x4t(uint32_t addr, uint32_t r[4]) {
    asm volatile("ldmatrix.sync.aligned.m8n8.x4.trans.shared.b16 {%0,%1,%2,%3}, [%4];"
                 : "=r"(r[0]), "=r"(r[1]), "=r"(r[2]), "=r"(r[3]) : "r"(addr));
}
__device__ __forceinline__ void mma_f16(float c[4], const uint32_t a[4], const uint32_t b0, const uint32_t b1) {
    asm volatile("mma.sync.aligned.m16n8k16.row.col.f32.f16.f16.f32 "
                 "{%0,%1,%2,%3}, {%4,%5,%6,%7}, {%8,%9}, {%0,%1,%2,%3};"
                 : "+f"(c[0]), "+f"(c[1]), "+f"(c[2]), "+f"(c[3])
                 : "r"(a[0]), "r"(a[1]), "r"(a[2]), "r"(a[3]), "r"(b0), "r"(b1));
}
__device__ __forceinline__ uint32_t h2(float a, float b) {
    __half2 t = __floats2half2_rn(a, b);
    return *(uint32_t*)&t;
}
__device__ __forceinline__ uint32_t ex2_f16x2(uint32_t x) {
    uint32_t r;
    asm("ex2.approx.f16x2 %0, %1;" : "=r"(r) : "r"(x));
    return r;
}
__device__ __forceinline__ float ex2f(float x) {
    float r;
    asm("ex2.approx.f32 %0, %1;" : "=f"(r) : "f"(x));
    return r;
}
__device__ __forceinline__ float tanh_ap(float x) {
    float r;
    asm("tanh.approx.f32 %0, %1;" : "=f"(r) : "f"(x));
    return r;
}
__device__ __forceinline__ float gelu_t(float v) {
    float t = tanh_ap(0.7978845608028654f * (v + 0.044715f * v * v * v));
    return 0.5f * v * (1.0f + t);
}
#define ONES_H2 0x3C003C00u   // (1.0h, 1.0h)
#define QSCL 0.1803368801111204f   // (1/sqrt(64)) * log2(e)

// ==================== scratch (device globals) ====================
__device__ __half g_h[TOK*EMB];
__device__ __half g_qkv[TOK*QKV_LD];
__device__ __half g_ctx[TOK*EMB];
__device__ float  g_x1[TOK*EMB];
__device__ __half g_mid[TOK*FF];
__device__ __half g_wqkv[QKV_LD*EMB];   // [N=3072][K=1024]
__device__ __half g_wo[EMB*EMB];
__device__ __half g_w1[EMB*FF];         // [N=FF][K=EMB]
__device__ __half g_w2[FF*EMB];         // [N=EMB][K=FF]

// ==================== batched square transpose ====================
__global__ __launch_bounds__(256) void transpose4_kernel(
    const float* __restrict__ Wq, const float* __restrict__ Wk,
    const float* __restrict__ Wv, const float* __restrict__ Wo,
    __half* __restrict__ Tq, __half* __restrict__ Tk,
    __half* __restrict__ Tv, __half* __restrict__ To)
{
    __shared__ float t[32][33];
    const float* W = (blockIdx.z == 0) ? Wq : (blockIdx.z == 1) ? Wk : (blockIdx.z == 2) ? Wv : Wo;
    __half*      T = (blockIdx.z == 0) ? Tq : (blockIdx.z == 1) ? Tk : (blockIdx.z == 2) ? Tv : To;
    int tx = threadIdx.x & 31, ty = threadIdx.x >> 5;
    int k0 = blockIdx.y * 32, n0 = blockIdx.x * 32;
    #pragma unroll
    for (int i = 0; i < 4; i++)
        t[ty + i*8][tx] = W[(size_t)(k0 + ty + i*8) * EMB + n0 + tx];
    __syncthreads();
    #pragma unroll
    for (int i = 0; i < 4; i++)
        T[(size_t)(n0 + ty + i*8) * EMB + k0 + tx] = __float2half_rn(t[tx][ty + i*8]);
}

// ==================== rect transpose ====================
__global__ __launch_bounds__(256) void transpose_half_kernel(
    const float* __restrict__ W, __half* __restrict__ T, int K, int N)
{
    __shared__ float t[32][33];
    int tx = threadIdx.x & 31, ty = threadIdx.x >> 5;
    int k0 = blockIdx.y * 32, n0 = blockIdx.x * 32;
    #pragma unroll
    for (int i = 0; i < 4; i++)
        t[ty + i*8][tx] = W[(size_t)(k0 + ty + i*8) * N + n0 + tx];
    __syncthreads();
    #pragma unroll
    for (int i = 0; i < 4; i++)
        T[(size_t)(n0 + ty + i*8) * K + k0 + tx] = __float2half_rn(t[tx][ty + i*8]);
}

// ==================== LayerNorm -> fp16, warp-per-row, 4 rows / 128-thread CTA ====================
__global__ __launch_bounds__(128) void ln_half_kernel(
    const float* __restrict__ X, const float* __restrict__ scale,
    const float* __restrict__ shift, __half* __restrict__ Y)
{
    const int lane = threadIdx.x & 31;
    const int row  = blockIdx.x * 4 + (threadIdx.x >> 5);
    const float* x = X + (size_t)row * EMB;

    float4 v[8];
    float s = 0.0f;
    #pragma unroll
    for (int i = 0; i < 8; i++) {
        v[i] = *(const float4*)(x + (i * 32 + lane) * 4);
        s += v[i].x + v[i].y + v[i].z + v[i].w;
    }
    #pragma unroll
    for (int o = 16; o > 0; o >>= 1) s += __shfl_xor_sync(0xffffffffu, s, o);
    float mean = s * (1.0f / EMB);

    float sq = 0.0f;
    #pragma unroll
    for (int i = 0; i < 8; i++) {
        v[i].x -= mean; v[i].y -= mean; v[i].z -= mean; v[i].w -= mean;
        sq += v[i].x*v[i].x + v[i].y*v[i].y + v[i].z*v[i].z + v[i].w*v[i].w;
    }
    #pragma unroll
    for (int o = 16; o > 0; o >>= 1) sq += __shfl_xor_sync(0xffffffffu, sq, o);
    float rstd = rsqrtf(sq * (1.0f / EMB) + 1e-5f);

    #pragma unroll
    for (int i = 0; i < 8; i++) {
        int c0 = (i * 32 + lane) * 4;
        float4 sc = *(const float4*)(scale + c0);
        float4 sh = *(const float4*)(shift + c0);
        size_t o = (size_t)row * EMB + c0;
        *(uint32_t*)(Y + o)     = h2(sc.x * v[i].x * rstd + sh.x, sc.y * v[i].y * rstd + sh.y);
        *(uint32_t*)(Y + o + 2) = h2(sc.z * v[i].z * rstd + sh.z, sc.w * v[i].w * rstd + sh.w);
    }
}

// ==================== fp16 mma.sync GEMM, 3-stage cp.async, 2 CTAs/SM ====================
// C[M][N] = A[M][K] @ B[N][K]^T. CTA tile MT x 128 (MT = 128 or 64), K-chunk 64.
// EPI: 1 +bias+res -> fp32; 2 +bias GELU -> fp16; 3 plain -> fp16 (Q cols scaled by QSCL)
template<int EPI, int MT>
__global__ __launch_bounds__(256, 2)
void gemm_kernel(
    const __half* __restrict__ A, const __half* __restrict__ B,
    const float* __restrict__ bias, const float* __restrict__ res,
    float* __restrict__ C, __half* __restrict__ Ch,
    int M, int N, int K)
{
    constexpr int MI = MT / 32;
    constexpr int A_BYTES = MT * 128;
    constexpr int STG = A_BYTES + 16384;

    extern __shared__ char smraw[];
    const uint32_t sbase = smem_u32(smraw);
    const int tid = threadIdx.x;
    const int bm = blockIdx.y, bn = blockIdx.x;

    const int w = tid >> 5, lane = tid & 31;
    const int wm = w & 1, wn = w >> 1;

    const int rowA = (lane & 7) + ((lane >> 3) & 1) * 8;
    const int chA  = (lane >> 4) & 1;
    const int gB   = lane >> 3;
    const int rB   = lane & 7;

    float acc[MI][4][4];
    #pragma unroll
    for (int i = 0; i < MI; i++)
        #pragma unroll
        for (int j = 0; j < 4; j++)
            #pragma unroll
            for (int q = 0; q < 4; q++) acc[i][j][q] = 0.0f;

    const int nchunk = K >> 6;

    auto stage = [&](int s, int c) {
        const uint32_t sb = sbase + s * STG;
        #pragma unroll
        for (int j = 0; j < MT / 32; ++j) {
            int idx = tid + j * 256;
            int r = idx >> 3, seg = idx & 7;
            cp_async16(sb + SWZ((uint32_t)(r * 128 + seg * 16)),
                       A + (size_t)(bm * MT + r) * K + c * 64 + seg * 8);
        }
        #pragma unroll
        for (int j = 0; j < 4; ++j) {
            int idx = tid + j * 256;
            int r = idx >> 3, seg = idx & 7;
            cp_async16(sb + A_BYTES + SWZ((uint32_t)(r * 128 + seg * 16)),
                       B + (size_t)(bn * 128 + r) * K + c * 64 + seg * 8);
        }
    };

    stage(0, 0); CP_COMMIT();
    if (nchunk > 1) { stage(1, 1); CP_COMMIT(); }

    for (int c = 0; c < nchunk; ++c) {
        const int s = c % 3;
        if (c == nchunk - 1) { CP_WAIT0(); } else { CP_WAIT1(); }
        __syncthreads();
        if (c + 2 < nchunk) { stage((c + 2) % 3, c + 2); CP_COMMIT(); }

        const uint32_t sA = sbase + s * STG;
        const uint32_t sB = sA + A_BYTES;

        #pragma unroll
        for (int ks = 0; ks < 4; ++ks) {
            uint32_t ah[MI][4], bh[2][4];
            #pragma unroll
            for (int mi = 0; mi < MI; ++mi) {
                uint32_t off = (uint32_t)((wm * (MT/2) + mi * 16 + rowA) * 128 + (ks * 2 + chA) * 16);
                ldsm_x4(sA + SWZ(off), ah[mi]);
            }
            #pragma unroll
            for (int nb = 0; nb < 2; ++nb) {
                uint32_t off = (uint32_t)((wn * 32 + nb * 16 + (gB >> 1) * 8 + rB) * 128
                                          + ks * 32 + (gB & 1) * 16);
                ldsm_x4(sB + SWZ(off), bh[nb]);
            }
            #pragma unroll
            for (int mi = 0; mi < MI; ++mi)
                #pragma unroll
                for (int ni = 0; ni < 4; ++ni)
                    mma_f16(acc[mi][ni], ah[mi], bh[ni>>1][(ni&1)*2], bh[ni>>1][(ni&1)*2+1]);
        }
    }

    // epilogue
    const int g = lane >> 2, tid4 = lane & 3;
    #pragma unroll
    for (int mi = 0; mi < MI; ++mi) {
        #pragma unroll
        for (int half_ = 0; half_ < 2; ++half_) {
            const size_t row = (size_t)(bm * MT + wm * (MT/2) + mi * 16 + g + half_ * 8);
            #pragma unroll
            for (int ni = 0; ni < 4; ++ni) {
                const int col = bn * 128 + wn * 32 + ni * 8 + tid4 * 2;
                float v0 = acc[mi][ni][half_ * 2 + 0];
                float v1 = acc[mi][ni][half_ * 2 + 1];
                if (EPI == 1) {
                    float2 rv = *(const float2*)(res + row * N + col);
                    float2 bv = *(const float2*)(bias + col);
                    *(float2*)(C + row * N + col) =
                        make_float2(v0 + bv.x + rv.x, v1 + bv.y + rv.y);
                } else if (EPI == 2) {
                    float2 bv = *(const float2*)(bias + col);
                    *(uint32_t*)(Ch + row * N + col) =
                        h2(gelu_t(v0 + bv.x), gelu_t(v1 + bv.y));
                } else {
                    // EPI==3 (QKV): fold softmax scale into Q columns (col < EMB)
                    if (col < EMB) { v0 *= QSCL; v1 *= QSCL; }
                    *(uint32_t*)(Ch + row * N + col) = h2(v0, v1);
                }
            }
        }
    }
}

#define GEMM_SMEM_128 (3 * (128*128 + 16384))
#define GEMM_SMEM_64  (3 * ( 64*128 + 16384))

// ==================== fp16 HMMA causal flash attention, 3-stage KV ====================
// Q pre-scaled by QSCL in the QKV epilogue -> S accumulators are already log2-domain.
#define ATTN_SMEM 65536

__global__ __launch_bounds__(256, 2) void attn_kernel(
    const __half* __restrict__ QKV, __half* __restrict__ O)
{
    extern __shared__ char smraw[];
    const uint32_t sbase = smem_u32(smraw);
    const uint32_t sQ = sbase;

    const int qb = gridDim.x - 1 - blockIdx.x;    // heavy tiles first
    const int h = blockIdx.y, b = blockIdx.z;
    const int tid = threadIdx.x;
    const int w = tid >> 5, lane = tid & 31;
    const int wq0 = w * 16;
    const int g = lane >> 2, c2 = (lane & 3) * 2;
    const size_t rows0 = (size_t)b * SEQ;
    const int hoff = h * HD;

    const int rowA = (lane & 7) + ((lane >> 3) & 1) * 8;
    const int chA  = (lane >> 4) & 1;
    const int gB   = lane >> 3;
    const int rB   = lane & 7;
    const int rowV = lane & 15;
    const int colV = (lane >> 4) * 8;

    for (int i = tid; i < 1024; i += 256) {
        int r = i >> 3, seg = i & 7;
        *(uint4*)(smraw + SWZ((uint32_t)(r * 128 + seg * 16))) =
            *(const uint4*)(QKV + (rows0 + qb * 128 + r) * QKV_LD + hoff + seg * 8);
    }

    auto stageKV = [&](int s, int jb) {
        uint32_t sb = sbase + 16384u + (uint32_t)s * 16384u;
        for (int i = tid; i < 512; i += 256) {
            int r = i >> 3, seg = i & 7;
            const size_t go = (rows0 + jb * 64 + r) * QKV_LD + hoff + seg * 8;
            uint32_t dst = SWZ((uint32_t)(r * 128 + seg * 16));
            cp_async16(sb + dst,         QKV + go + EMB);
            cp_async16(sb + 8192u + dst, QKV + go + 2 * EMB);
        }
    };

    float oacc[8][4];
    #pragma unroll
    for (int i = 0; i < 8; i++)
        #pragma unroll
        for (int q = 0; q < 4; q++) oacc[i][q] = 0.0f;
    float m0 = -1e30f, m1 = -1e30f, l0 = 0.0f, l1 = 0.0f;

    uint32_t qfrag[4][4];

    const int row0 = qb * 128 + wq0 + g;
    const int row1 = row0 + 8;
    const int njb = 2 * qb + 2;

    stageKV(0, 0); CP_COMMIT();
    if (njb > 1) { stageKV(1, 1); CP_COMMIT(); }

    for (int jb = 0; jb < njb; ++jb) {
        if (jb == njb - 1)      { CP_WAIT0(); }
        else if (jb == njb - 2) { CP_WAIT1(); }
        else                    { CP_WAIT2(); }
        __syncthreads();
        if (jb + 2 < njb) { stageKV((jb + 2) % 3, jb + 2); CP_COMMIT(); }

        if (jb == 0) {
            #pragma unroll
            for (int ks = 0; ks < 4; ++ks)
                ldsm_x4(sQ + SWZ((uint32_t)((wq0 + rowA) * 128 + (ks * 2 + chA) * 16)), qfrag[ks]);
        }

        const uint32_t sK = sbase + 16384u + (uint32_t)(jb % 3) * 16384u;
        const uint32_t sV = sK + 8192u;

        // S = Q K^T (already log2-domain: Q pre-scaled)
        float sacc[8][4];
        #pragma unroll
        for (int i = 0; i < 8; i++)
            #pragma unroll
            for (int q = 0; q < 4; q++) sacc[i][q] = 0.0f;

        #pragma unroll
        for (int ks = 0; ks < 4; ++ks) {
            #pragma unroll
            for (int nb = 0; nb < 4; ++nb) {
                uint32_t bk[4];
                ldsm_x4(sK + SWZ((uint32_t)((nb * 16 + (gB >> 1) * 8 + rB) * 128
                                            + ks * 32 + (gB & 1) * 16)), bk);
                mma_f16(sacc[nb*2+0], qfrag[ks], bk[0], bk[1]);
                mma_f16(sacc[nb*2+1], qfrag[ks], bk[2], bk[3]);
            }
        }

        // causal mask only on diagonal KV blocks
        if (jb >= 2 * qb) {
            const int col0 = jb * 64;
            #pragma unroll
            for (int ni = 0; ni < 8; ++ni) {
                int cg = col0 + ni * 8 + c2;
                if (cg     > row0) sacc[ni][0] = -1e30f;
                if (cg + 1 > row0) sacc[ni][1] = -1e30f;
                if (cg     > row1) sacc[ni][2] = -1e30f;
                if (cg + 1 > row1) sacc[ni][3] = -1e30f;
            }
        }

        float rmax0 = -1e30f, rmax1 = -1e30f;
        #pragma unroll
        for (int ni = 0; ni < 8; ++ni) {
            rmax0 = fmaxf(rmax0, fmaxf(sacc[ni][0], sacc[ni][1]));
            rmax1 = fmaxf(rmax1, fmaxf(sacc[ni][2], sacc[ni][3]));
        }
        #pragma unroll
        for (int o = 1; o <= 2; o <<= 1) {
            rmax0 = fmaxf(rmax0, __shfl_xor_sync(0xffffffffu, rmax0, o));
            rmax1 = fmaxf(rmax1, __shfl_xor_sync(0xffffffffu, rmax1, o));
        }
        float mn0 = fmaxf(m0, rmax0), mn1 = fmaxf(m1, rmax1);
        float alpha0 = ex2f(m0 - mn0), alpha1 = ex2f(m1 - mn1);
        m0 = mn0; m1 = mn1;
        #pragma unroll
        for (int ni = 0; ni < 8; ++ni) {
            oacc[ni][0] *= alpha0; oacc[ni][1] *= alpha0;
            oacc[ni][2] *= alpha1; oacc[ni][3] *= alpha1;
        }

        uint32_t pw[8][2];
        #pragma unroll
        for (int ni = 0; ni < 8; ++ni) {
            pw[ni][0] = ex2_f16x2(h2(sacc[ni][0] - mn0, sacc[ni][1] - mn0));
            pw[ni][1] = ex2_f16x2(h2(sacc[ni][2] - mn1, sacc[ni][3] - mn1));
        }

        float rsum[4] = {0.0f, 0.0f, 0.0f, 0.0f};
        #pragma unroll
        for (int kb = 0; kb < 4; ++kb) {
            uint32_t pa[4] = { pw[2*kb][0], pw[2*kb][1], pw[2*kb+1][0], pw[2*kb+1][1] };
            mma_f16(rsum, pa, ONES_H2, ONES_H2);
            #pragma unroll
            for (int nv = 0; nv < 4; ++nv) {
                uint32_t vv[4];
                ldsm_x4t(sV + SWZ((uint32_t)((kb * 16 + rowV) * 128 + (nv * 16 + colV) * 2)), vv);
                mma_f16(oacc[nv*2+0], pa, vv[0], vv[1]);
                mma_f16(oacc[nv*2+1], pa, vv[2], vv[3]);
            }
        }
        l0 = l0 * alpha0 + rsum[0];
        l1 = l1 * alpha1 + rsum[2];
    }

    float il0 = 1.0f / l0, il1 = 1.0f / l1;
    const size_t gr0 = (rows0 + qb * 128 + wq0 + g) * EMB + hoff;
    const size_t gr1 = gr0 + 8 * EMB;
    #pragma unroll
    for (int ni = 0; ni < 8; ++ni) {
        int col = ni * 8 + c2;
        *(uint32_t*)(O + gr0 + col) = h2(oacc[ni][0] * il0, oacc[ni][1] * il0);
        *(uint32_t*)(O + gr1 + col) = h2(oacc[ni][2] * il1, oacc[ni][3] * il1);
    }
}

// ==================== host launch ====================
extern "C" void kernel_launch(void* const* d_in, const int* in_sizes, int n_in,
                              void* d_out, int out_size)
{
    const float* x    = (const float*)d_in[0];
    const float* Wq   = (const float*)d_in[1];
    const float* Wk   = (const float*)d_in[2];
    const float* Wv   = (const float*)d_in[3];
    const float* Wo   = (const float*)d_in[4];
    const float* bo   = (const float*)d_in[5];
    const float* W1   = (const float*)d_in[6];
    const float* b1   = (const float*)d_in[7];
    const float* W2   = (const float*)d_in[8];
    const float* b2   = (const float*)d_in[9];
    const float* ln1s = (const float*)d_in[10];
    const float* ln1b = (const float*)d_in[11];
    const float* ln2s = (const float*)d_in[12];
    const float* ln2b = (const float*)d_in[13];
    float* out = (float*)d_out;

    __half *hh, *qkv, *ctx, *mid, *wqkv, *wo, *w1, *w2;
    float *x1;
    cudaGetSymbolAddress((void**)&hh,   g_h);
    cudaGetSymbolAddress((void**)&qkv,  g_qkv);
    cudaGetSymbolAddress((void**)&ctx,  g_ctx);
    cudaGetSymbolAddress((void**)&x1,   g_x1);
    cudaGetSymbolAddress((void**)&mid,  g_mid);
    cudaGetSymbolAddress((void**)&wqkv, g_wqkv);
    cudaGetSymbolAddress((void**)&wo,   g_wo);
    cudaGetSymbolAddress((void**)&w1,   g_w1);
    cudaGetSymbolAddress((void**)&w2,   g_w2);

    cudaFuncSetAttribute(gemm_kernel<1,64>,  cudaFuncAttributeMaxDynamicSharedMemorySize, GEMM_SMEM_64);
    cudaFuncSetAttribute(gemm_kernel<2,128>, cudaFuncAttributeMaxDynamicSharedMemorySize, GEMM_SMEM_128);
    cudaFuncSetAttribute(gemm_kernel<3,128>, cudaFuncAttributeMaxDynamicSharedMemorySize, GEMM_SMEM_128);
    cudaFuncSetAttribute(attn_kernel, cudaFuncAttributeMaxDynamicSharedMemorySize, ATTN_SMEM);

    static cudaStream_t s_side = []{
        cudaStream_t s; cudaStreamCreateWithFlags(&s, cudaStreamNonBlocking); return s; }();
    static cudaEvent_t ev_fork = []{
        cudaEvent_t e; cudaEventCreateWithFlags(&e, cudaEventDisableTiming); return e; }();
    static cudaEvent_t ev_a = []{
        cudaEvent_t e; cudaEventCreateWithFlags(&e, cudaEventDisableTiming); return e; }();
    static cudaEvent_t ev_b = []{
        cudaEvent_t e; cudaEventCreateWithFlags(&e, cudaEventDisableTiming); return e; }();

    // fork: weight transposes on side stream, concurrent with LN1
    cudaEventRecord(ev_fork, 0);
    cudaStreamWaitEvent(s_side, ev_fork, 0);
    transpose4_kernel<<<dim3(EMB/32, EMB/32, 4), 256, 0, s_side>>>(
        Wq, Wk, Wv, Wo, wqkv, wqkv + EMB*EMB, wqkv + 2*EMB*EMB, wo);
    cudaEventRecord(ev_a, s_side);
    transpose_half_kernel<<<dim3(FF/32,  EMB/32), 256, 0, s_side>>>(W1, w1, EMB, FF);
    transpose_half_kernel<<<dim3(EMB/32, FF/32),  256, 0, s_side>>>(W2, w2, FF, EMB);
    cudaEventRecord(ev_b, s_side);

    // main: LN1 concurrent with transpose4
    ln_half_kernel<<<TOK/4, 128>>>(x, ln1s, ln1b, hh);
    cudaStreamWaitEvent(0, ev_a, 0);

    // fused QKV projection -> fp16 (MT=128; Q columns pre-scaled)
    gemm_kernel<3,128><<<dim3(QKV_LD/128, TOK/128), 256, GEMM_SMEM_128>>>(
        hh, wqkv, nullptr, nullptr, nullptr, qkv, TOK, QKV_LD, EMB);

    // attention -> ctx fp16
    attn_kernel<<<dim3(SEQ/128, HEADS, BATCH), 256, ATTN_SMEM>>>(qkv, ctx);

    // Wo + bias + residual -> x1 (MT=64: 512 CTAs — measured win)
    gemm_kernel<1,64><<<dim3(EMB/128, TOK/64), 256, GEMM_SMEM_64>>>(
        ctx, wo, bo, x, x1, nullptr, TOK, EMB, EMB);

    // LN2 -> h fp16
    ln_half_kernel<<<TOK/4, 128>>>(x1, ln2s, ln2b, hh);

    cudaStreamWaitEvent(0, ev_b, 0);

    // FFN up + GELU -> mid fp16 (MT=128)
    gemm_kernel<2,128><<<dim3(FF/128, TOK/128), 256, GEMM_SMEM_128>>>(
        hh, w1, b1, nullptr, nullptr, mid, TOK, FF, EMB);

    // FFN down + bias + residual -> out (MT=64)
    gemm_kernel<1,64><<<dim3(EMB/128, TOK/64), 256, GEMM_SMEM_64>>>(
        mid, w2, b2, x1, out, nullptr, TOK, EMB, FF);
}

// round 15
// speedup vs baseline: 1.0543x; 1.0098x over previous
#include <cuda_runtime.h>
#include <cuda_fp16.h>
#include <math.h>
#include <float.h>
#include <stdint.h>

#define BATCH 2
#define SEQ   2048
#define TOK   (BATCH*SEQ)        // 4096
#define EMB   1024
#define HEADS 16
#define HD    64
#define FF    4096
#define QKV_LD 3072

// ==================== helpers ====================
__device__ __forceinline__ uint32_t smem_u32(const void* p) {
    uint32_t a;
    asm("{ .reg .u64 t; cvta.to.shared.u64 t, %1; cvt.u32.u64 %0, t; }" : "=r"(a) : "l"(p));
    return a;
}
#define SWZ(x) ((x) ^ (((x) >> 3) & 0x70))

__device__ __forceinline__ void cp_async16(uint32_t saddr, const void* gptr) {
    asm volatile("cp.async.cg.shared.global [%0], [%1], 16;" :: "r"(saddr), "l"(gptr));
}
#define CP_COMMIT() asm volatile("cp.async.commit_group;" ::: "memory")
#define CP_WAIT2()  asm volatile("cp.async.wait_group 2;" ::: "memory")
#define CP_WAIT1()  asm volatile("cp.async.wait_group 1;" ::: "memory")
#define CP_WAIT0()  asm volatile("cp.async.wait_group 0;" ::: "memory")

__device__ __forceinline__ void ldsm_x4(uint32_t addr, uint32_t r[4]) {
    asm volatile("ldmatrix.sync.aligned.m8n8.x4.shared.b16 {%0,%1,%2,%3}, [%4];"
                 : "=r"(r[0]), "=r"(r[1]), "=r"(r[2]), "=r"(r[3]) : "r"(addr));
}
__device__ __forceinline__ void ldsm_x4t(uint32_t addr, uint32_t r[4]) {
    asm volatile("ldmatrix.sync.aligned.m8n8.x4.trans.shared.b16 {%0,%1,%2,%3}, [%4];"
                 : "=r"(r[0]), "=r"(r[1]), "=r"(r[2]), "=r"(r[3]) : "r"(addr));
}
__device__ __forceinline__ void mma_f16(float c[4], const uint32_t a[4], const uint32_t b0, const uint32_t b1) {
    asm volatile("mma.sync.aligned.m16n8k16.row.col.f32.f16.f16.f32 "
                 "{%0,%1,%2,%3}, {%4,%5,%6,%7}, {%8,%9}, {%0,%1,%2,%3};"
                 : "+f"(c[0]), "+f"(c[1]), "+f"(c[2]), "+f"(c[3])
                 : "r"(a[0]), "r"(a[1]), "r"(a[2]), "r"(a[3]), "r"(b0), "r"(b1));
}
__device__ __forceinline__ uint32_t h2(float a, float b) {
    __half2 t = __floats2half2_rn(a, b);
    return *(uint32_t*)&t;
}
__device__ __forceinline__ uint32_t ex2_f16x2(uint32_t x) {
    uint32_t r;
    asm("ex2.approx.f16x2 %0, %1;" : "=r"(r) : "r"(x));
    return r;
}
__device__ __forceinline__ float ex2f(float x) {
    float r;
    asm("ex2.approx.f32 %0, %1;" : "=f"(r) : "f"(x));
    return r;
}
__device__ __forceinline__ float tanh_ap(float x) {
    float r;
    asm("tanh.approx.f32 %0, %1;" : "=f"(r) : "f"(x));
    return r;
}
__device__ __forceinline__ float gelu_t(float v) {
    float t = tanh_ap(0.7978845608028654f * (v + 0.044715f * v * v * v));
    return 0.5f * v * (1.0f + t);
}
__device__ __forceinline__ float sum2_h2(uint32_t w) {
    float2 f = __half22float2(*(__half2*)&w);
    return f.x + f.y;
}
#define QSCL 0.1803368801111204f   // (1/sqrt(64)) * log2(e)

// ==================== scratch (device globals) ====================
__device__ __half g_h[TOK*EMB];
__device__ __half g_qkv[TOK*QKV_LD];
__device__ __half g_ctx[TOK*EMB];
__device__ float  g_x1[TOK*EMB];
__device__ __half g_mid[TOK*FF];
__device__ __half g_wqkv[QKV_LD*EMB];   // [N=3072][K=1024]
__device__ __half g_wo[EMB*EMB];
__device__ __half g_w1[EMB*FF];         // [N=FF][K=EMB]
__device__ __half g_w2[FF*EMB];         // [N=EMB][K=FF]

// ==================== batched square transpose ====================
__global__ __launch_bounds__(256) void transpose4_kernel(
    const float* __restrict__ Wq, const float* __restrict__ Wk,
    const float* __restrict__ Wv, const float* __restrict__ Wo,
    __half* __restrict__ Tq, __half* __restrict__ Tk,
    __half* __restrict__ Tv, __half* __restrict__ To)
{
    __shared__ float t[32][33];
    const float* W = (blockIdx.z == 0) ? Wq : (blockIdx.z == 1) ? Wk : (blockIdx.z == 2) ? Wv : Wo;
    __half*      T = (blockIdx.z == 0) ? Tq : (blockIdx.z == 1) ? Tk : (blockIdx.z == 2) ? Tv : To;
    int tx = threadIdx.x & 31, ty = threadIdx.x >> 5;
    int k0 = blockIdx.y * 32, n0 = blockIdx.x * 32;
    #pragma unroll
    for (int i = 0; i < 4; i++)
        t[ty + i*8][tx] = W[(size_t)(k0 + ty + i*8) * EMB + n0 + tx];
    __syncthreads();
    #pragma unroll
    for (int i = 0; i < 4; i++)
        T[(size_t)(n0 + ty + i*8) * EMB + k0 + tx] = __float2half_rn(t[tx][ty + i*8]);
}

// ==================== rect transpose ====================
__global__ __launch_bounds__(256) void transpose_half_kernel(
    const float* __restrict__ W, __half* __restrict__ T, int K, int N)
{
    __shared__ float t[32][33];
    int tx = threadIdx.x & 31, ty = threadIdx.x >> 5;
    int k0 = blockIdx.y * 32, n0 = blockIdx.x * 32;
    #pragma unroll
    for (int i = 0; i < 4; i++)
        t[ty + i*8][tx] = W[(size_t)(k0 + ty + i*8) * N + n0 + tx];
    __syncthreads();
    #pragma unroll
    for (int i = 0; i < 4; i++)
        T[(size_t)(n0 + ty + i*8) * K + k0 + tx] = __float2half_rn(t[tx][ty + i*8]);
}

// ==================== LayerNorm -> fp16, warp-per-row, 4 rows / 128-thread CTA ====================
__global__ __launch_bounds__(128) void ln_half_kernel(
    const float* __restrict__ X, const float* __restrict__ scale,
    const float* __restrict__ shift, __half* __restrict__ Y)
{
    const int lane = threadIdx.x & 31;
    const int row  = blockIdx.x * 4 + (threadIdx.x >> 5);
    const float* x = X + (size_t)row * EMB;

    float4 v[8];
    float s = 0.0f;
    #pragma unroll
    for (int i = 0; i < 8; i++) {
        v[i] = *(const float4*)(x + (i * 32 + lane) * 4);
        s += v[i].x + v[i].y + v[i].z + v[i].w;
    }
    #pragma unroll
    for (int o = 16; o > 0; o >>= 1) s += __shfl_xor_sync(0xffffffffu, s, o);
    float mean = s * (1.0f / EMB);

    float sq = 0.0f;
    #pragma unroll
    for (int i = 0; i < 8; i++) {
        v[i].x -= mean; v[i].y -= mean; v[i].z -= mean; v[i].w -= mean;
        sq += v[i].x*v[i].x + v[i].y*v[i].y + v[i].z*v[i].z + v[i].w*v[i].w;
    }
    #pragma unroll
    for (int o = 16; o > 0; o >>= 1) sq += __shfl_xor_sync(0xffffffffu, sq, o);
    float rstd = rsqrtf(sq * (1.0f / EMB) + 1e-5f);

    #pragma unroll
    for (int i = 0; i < 8; i++) {
        int c0 = (i * 32 + lane) * 4;
        float4 sc = *(const float4*)(scale + c0);
        float4 sh = *(const float4*)(shift + c0);
        size_t o = (size_t)row * EMB + c0;
        *(uint32_t*)(Y + o)     = h2(sc.x * v[i].x * rstd + sh.x, sc.y * v[i].y * rstd + sh.y);
        *(uint32_t*)(Y + o + 2) = h2(sc.z * v[i].z * rstd + sh.z, sc.w * v[i].w * rstd + sh.w);
    }
}

// ==================== fp16 mma.sync GEMM, NS-stage cp.async, 2 CTAs/SM ====================
// C[M][N] = A[M][K] @ B[N][K]^T. CTA tile MT x 128, K-chunk 64, NS smem stages.
// EPI: 1 +bias+res -> fp32; 2 +bias GELU -> fp16; 3 plain -> fp16 (Q cols scaled by QSCL)
template<int EPI, int MT, int NS>
__global__ __launch_bounds__(256, 2)
void gemm_kernel(
    const __half* __restrict__ A, const __half* __restrict__ B,
    const float* __restrict__ bias, const float* __restrict__ res,
    float* __restrict__ C, __half* __restrict__ Ch,
    int M, int N, int K)
{
    constexpr int MI = MT / 32;
    constexpr int A_BYTES = MT * 128;
    constexpr int STG = A_BYTES + 16384;

    extern __shared__ char smraw[];
    const uint32_t sbase = smem_u32(smraw);
    const int tid = threadIdx.x;
    const int bm = blockIdx.y, bn = blockIdx.x;

    const int w = tid >> 5, lane = tid & 31;
    const int wm = w & 1, wn = w >> 1;

    const int rowA = (lane & 7) + ((lane >> 3) & 1) * 8;
    const int chA  = (lane >> 4) & 1;
    const int gB   = lane >> 3;
    const int rB   = lane & 7;

    float acc[MI][4][4];
    #pragma unroll
    for (int i = 0; i < MI; i++)
        #pragma unroll
        for (int j = 0; j < 4; j++)
            #pragma unroll
            for (int q = 0; q < 4; q++) acc[i][j][q] = 0.0f;

    const int nchunk = K >> 6;

    auto stage = [&](int s, int c) {
        const uint32_t sb = sbase + s * STG;
        #pragma unroll
        for (int j = 0; j < MT / 32; ++j) {
            int idx = tid + j * 256;
            int r = idx >> 3, seg = idx & 7;
            cp_async16(sb + SWZ((uint32_t)(r * 128 + seg * 16)),
                       A + (size_t)(bm * MT + r) * K + c * 64 + seg * 8);
        }
        #pragma unroll
        for (int j = 0; j < 4; ++j) {
            int idx = tid + j * 256;
            int r = idx >> 3, seg = idx & 7;
            cp_async16(sb + A_BYTES + SWZ((uint32_t)(r * 128 + seg * 16)),
                       B + (size_t)(bn * 128 + r) * K + c * 64 + seg * 8);
        }
    };

    // prologue: prefetch NS-1 chunks
    #pragma unroll
    for (int p = 0; p < NS - 1; ++p) {
        if (p < nchunk) { stage(p, p); CP_COMMIT(); }
    }

    for (int c = 0; c < nchunk; ++c) {
        const int s = c % NS;
        if (c >= nchunk - 1)      { CP_WAIT0(); }
        else if (c >= nchunk - 2) { CP_WAIT1(); }
        else if (NS == 3)         { CP_WAIT1(); }
        else                      { CP_WAIT2(); }
        __syncthreads();
        if (c + NS - 1 < nchunk) { stage((c + NS - 1) % NS, c + NS - 1); CP_COMMIT(); }

        const uint32_t sA = sbase + s * STG;
        const uint32_t sB = sA + A_BYTES;

        #pragma unroll
        for (int ks = 0; ks < 4; ++ks) {
            uint32_t ah[MI][4], bh[2][4];
            #pragma unroll
            for (int mi = 0; mi < MI; ++mi) {
                uint32_t off = (uint32_t)((wm * (MT/2) + mi * 16 + rowA) * 128 + (ks * 2 + chA) * 16);
                ldsm_x4(sA + SWZ(off), ah[mi]);
            }
            #pragma unroll
            for (int nb = 0; nb < 2; ++nb) {
                uint32_t off = (uint32_t)((wn * 32 + nb * 16 + (gB >> 1) * 8 + rB) * 128
                                          + ks * 32 + (gB & 1) * 16);
                ldsm_x4(sB + SWZ(off), bh[nb]);
            }
            #pragma unroll
            for (int mi = 0; mi < MI; ++mi)
                #pragma unroll
                for (int ni = 0; ni < 4; ++ni)
                    mma_f16(acc[mi][ni], ah[mi], bh[ni>>1][(ni&1)*2], bh[ni>>1][(ni&1)*2+1]);
        }
    }

    // epilogue
    const int g = lane >> 2, tid4 = lane & 3;
    #pragma unroll
    for (int mi = 0; mi < MI; ++mi) {
        #pragma unroll
        for (int half_ = 0; half_ < 2; ++half_) {
            const size_t row = (size_t)(bm * MT + wm * (MT/2) + mi * 16 + g + half_ * 8);
            #pragma unroll
            for (int ni = 0; ni < 4; ++ni) {
                const int col = bn * 128 + wn * 32 + ni * 8 + tid4 * 2;
                float v0 = acc[mi][ni][half_ * 2 + 0];
                float v1 = acc[mi][ni][half_ * 2 + 1];
                if (EPI == 1) {
                    float2 rv = *(const float2*)(res + row * N + col);
                    float2 bv = *(const float2*)(bias + col);
                    *(float2*)(C + row * N + col) =
                        make_float2(v0 + bv.x + rv.x, v1 + bv.y + rv.y);
                } else if (EPI == 2) {
                    float2 bv = *(const float2*)(bias + col);
                    *(uint32_t*)(Ch + row * N + col) =
                        h2(gelu_t(v0 + bv.x), gelu_t(v1 + bv.y));
                } else {
                    if (col < EMB) { v0 *= QSCL; v1 *= QSCL; }
                    *(uint32_t*)(Ch + row * N + col) = h2(v0, v1);
                }
            }
        }
    }
}

#define GEMM_SMEM_128 (3 * (128*128 + 16384))
#define GEMM_SMEM_64  (4 * ( 64*128 + 16384))

// ==================== fp16 HMMA causal flash attention, 3-stage KV ====================
// Q pre-scaled by QSCL -> S already log2-domain. Rowsums on fma/alu pipes (not tensor).
#define ATTN_SMEM 65536

__global__ __launch_bounds__(256, 2) void attn_kernel(
    const __half* __restrict__ QKV, __half* __restrict__ O)
{
    extern __shared__ char smraw[];
    const uint32_t sbase = smem_u32(smraw);
    const uint32_t sQ = sbase;

    const int qb = gridDim.x - 1 - blockIdx.x;    // heavy tiles first
    const int h = blockIdx.y, b = blockIdx.z;
    const int tid = threadIdx.x;
    const int w = tid >> 5, lane = tid & 31;
    const int wq0 = w * 16;
    const int g = lane >> 2, c2 = (lane & 3) * 2;
    const size_t rows0 = (size_t)b * SEQ;
    const int hoff = h * HD;

    const int rowA = (lane & 7) + ((lane >> 3) & 1) * 8;
    const int chA  = (lane >> 4) & 1;
    const int gB   = lane >> 3;
    const int rB   = lane & 7;
    const int rowV = lane & 15;
    const int colV = (lane >> 4) * 8;

    for (int i = tid; i < 1024; i += 256) {
        int r = i >> 3, seg = i & 7;
        *(uint4*)(smraw + SWZ((uint32_t)(r * 128 + seg * 16))) =
            *(const uint4*)(QKV + (rows0 + qb * 128 + r) * QKV_LD + hoff + seg * 8);
    }

    auto stageKV = [&](int s, int jb) {
        uint32_t sb = sbase + 16384u + (uint32_t)s * 16384u;
        for (int i = tid; i < 512; i += 256) {
            int r = i >> 3, seg = i & 7;
            const size_t go = (rows0 + jb * 64 + r) * QKV_LD + hoff + seg * 8;
            uint32_t dst = SWZ((uint32_t)(r * 128 + seg * 16));
            cp_async16(sb + dst,         QKV + go + EMB);
            cp_async16(sb + 8192u + dst, QKV + go + 2 * EMB);
        }
    };

    float oacc[8][4];
    #pragma unroll
    for (int i = 0; i < 8; i++)
        #pragma unroll
        for (int q = 0; q < 4; q++) oacc[i][q] = 0.0f;
    float m0 = -1e30f, m1 = -1e30f, l0 = 0.0f, l1 = 0.0f;

    uint32_t qfrag[4][4];

    const int row0 = qb * 128 + wq0 + g;
    const int row1 = row0 + 8;
    const int njb = 2 * qb + 2;

    stageKV(0, 0); CP_COMMIT();
    if (njb > 1) { stageKV(1, 1); CP_COMMIT(); }

    for (int jb = 0; jb < njb; ++jb) {
        if (jb == njb - 1)      { CP_WAIT0(); }
        else if (jb == njb - 2) { CP_WAIT1(); }
        else                    { CP_WAIT2(); }
        __syncthreads();
        if (jb + 2 < njb) { stageKV((jb + 2) % 3, jb + 2); CP_COMMIT(); }

        if (jb == 0) {
            #pragma unroll
            for (int ks = 0; ks < 4; ++ks)
                ldsm_x4(sQ + SWZ((uint32_t)((wq0 + rowA) * 128 + (ks * 2 + chA) * 16)), qfrag[ks]);
        }

        const uint32_t sK = sbase + 16384u + (uint32_t)(jb % 3) * 16384u;
        const uint32_t sV = sK + 8192u;

        // S = Q K^T (log2-domain)
        float sacc[8][4];
        #pragma unroll
        for (int i = 0; i < 8; i++)
            #pragma unroll
            for (int q = 0; q < 4; q++) sacc[i][q] = 0.0f;

        #pragma unroll
        for (int ks = 0; ks < 4; ++ks) {
            #pragma unroll
            for (int nb = 0; nb < 4; ++nb) {
                uint32_t bk[4];
                ldsm_x4(sK + SWZ((uint32_t)((nb * 16 + (gB >> 1) * 8 + rB) * 128
                                            + ks * 32 + (gB & 1) * 16)), bk);
                mma_f16(sacc[nb*2+0], qfrag[ks], bk[0], bk[1]);
                mma_f16(sacc[nb*2+1], qfrag[ks], bk[2], bk[3]);
            }
        }

        // causal mask only on diagonal KV blocks
        if (jb >= 2 * qb) {
            const int col0 = jb * 64;
            #pragma unroll
            for (int ni = 0; ni < 8; ++ni) {
                int cg = col0 + ni * 8 + c2;
                if (cg     > row0) sacc[ni][0] = -1e30f;
                if (cg + 1 > row0) sacc[ni][1] = -1e30f;
                if (cg     > row1) sacc[ni][2] = -1e30f;
                if (cg + 1 > row1) sacc[ni][3] = -1e30f;
            }
        }

        float rmax0 = -1e30f, rmax1 = -1e30f;
        #pragma unroll
        for (int ni = 0; ni < 8; ++ni) {
            rmax0 = fmaxf(rmax0, fmaxf(sacc[ni][0], sacc[ni][1]));
            rmax1 = fmaxf(rmax1, fmaxf(sacc[ni][2], sacc[ni][3]));
        }
        #pragma unroll
        for (int o = 1; o <= 2; o <<= 1) {
            rmax0 = fmaxf(rmax0, __shfl_xor_sync(0xffffffffu, rmax0, o));
            rmax1 = fmaxf(rmax1, __shfl_xor_sync(0xffffffffu, rmax1, o));
        }
        float mn0 = fmaxf(m0, rmax0), mn1 = fmaxf(m1, rmax1);
        float alpha0 = ex2f(m0 - mn0), alpha1 = ex2f(m1 - mn1);
        m0 = mn0; m1 = mn1;
        #pragma unroll
        for (int ni = 0; ni < 8; ++ni) {
            oacc[ni][0] *= alpha0; oacc[ni][1] *= alpha0;
            oacc[ni][2] *= alpha1; oacc[ni][3] *= alpha1;
        }

        // P = 2^(s - mn) as packed fp16; rowsums on fma pipe
        uint32_t pw[8][2];
        float rs0 = 0.0f, rs1 = 0.0f;
        #pragma unroll
        for (int ni = 0; ni < 8; ++ni) {
            pw[ni][0] = ex2_f16x2(h2(sacc[ni][0] - mn0, sacc[ni][1] - mn0));
            pw[ni][1] = ex2_f16x2(h2(sacc[ni][2] - mn1, sacc[ni][3] - mn1));
            rs0 += sum2_h2(pw[ni][0]);
            rs1 += sum2_h2(pw[ni][1]);
        }
        #pragma unroll
        for (int o = 1; o <= 2; o <<= 1) {
            rs0 += __shfl_xor_sync(0xffffffffu, rs0, o);
            rs1 += __shfl_xor_sync(0xffffffffu, rs1, o);
        }
        l0 = l0 * alpha0 + rs0;
        l1 = l1 * alpha1 + rs1;

        // O += P V (tensor pipe only for real work now)
        #pragma unroll
        for (int kb = 0; kb < 4; ++kb) {
            uint32_t pa[4] = { pw[2*kb][0], pw[2*kb][1], pw[2*kb+1][0], pw[2*kb+1][1] };
            #pragma unroll
            for (int nv = 0; nv < 4; ++nv) {
                uint32_t vv[4];
                ldsm_x4t(sV + SWZ((uint32_t)((kb * 16 + rowV) * 128 + (nv * 16 + colV) * 2)), vv);
                mma_f16(oacc[nv*2+0], pa, vv[0], vv[1]);
                mma_f16(oacc[nv*2+1], pa, vv[2], vv[3]);
            }
        }
    }

    float il0 = 1.0f / l0, il1 = 1.0f / l1;
    const size_t gr0 = (rows0 + qb * 128 + wq0 + g) * EMB + hoff;
    const size_t gr1 = gr0 + 8 * EMB;
    #pragma unroll
    for (int ni = 0; ni < 8; ++ni) {
        int col = ni * 8 + c2;
        *(uint32_t*)(O + gr0 + col) = h2(oacc[ni][0] * il0, oacc[ni][1] * il0);
        *(uint32_t*)(O + gr1 + col) = h2(oacc[ni][2] * il1, oacc[ni][3] * il1);
    }
}

// ==================== host launch ====================
extern "C" void kernel_launch(void* const* d_in, const int* in_sizes, int n_in,
                              void* d_out, int out_size)
{
    const float* x    = (const float*)d_in[0];
    const float* Wq   = (const float*)d_in[1];
    const float* Wk   = (const float*)d_in[2];
    const float* Wv   = (const float*)d_in[3];
    const float* Wo   = (const float*)d_in[4];
    const float* bo   = (const float*)d_in[5];
    const float* W1   = (const float*)d_in[6];
    const float* b1   = (const float*)d_in[7];
    const float* W2   = (const float*)d_in[8];
    const float* b2   = (const float*)d_in[9];
    const float* ln1s = (const float*)d_in[10];
    const float* ln1b = (const float*)d_in[11];
    const float* ln2s = (const float*)d_in[12];
    const float* ln2b = (const float*)d_in[13];
    float* out = (float*)d_out;

    __half *hh, *qkv, *ctx, *mid, *wqkv, *wo, *w1, *w2;
    float *x1;
    cudaGetSymbolAddress((void**)&hh,   g_h);
    cudaGetSymbolAddress((void**)&qkv,  g_qkv);
    cudaGetSymbolAddress((void**)&ctx,  g_ctx);
    cudaGetSymbolAddress((void**)&x1,   g_x1);
    cudaGetSymbolAddress((void**)&mid,  g_mid);
    cudaGetSymbolAddress((void**)&wqkv, g_wqkv);
    cudaGetSymbolAddress((void**)&wo,   g_wo);
    cudaGetSymbolAddress((void**)&w1,   g_w1);
    cudaGetSymbolAddress((void**)&w2,   g_w2);

    cudaFuncSetAttribute((const void*)gemm_kernel<1,64,4>,  cudaFuncAttributeMaxDynamicSharedMemorySize, GEMM_SMEM_64);
    cudaFuncSetAttribute((const void*)gemm_kernel<2,128,3>, cudaFuncAttributeMaxDynamicSharedMemorySize, GEMM_SMEM_128);
    cudaFuncSetAttribute((const void*)gemm_kernel<3,128,3>, cudaFuncAttributeMaxDynamicSharedMemorySize, GEMM_SMEM_128);
    cudaFuncSetAttribute(attn_kernel, cudaFuncAttributeMaxDynamicSharedMemorySize, ATTN_SMEM);

    static cudaStream_t s_side = []{
        cudaStream_t s; cudaStreamCreateWithFlags(&s, cudaStreamNonBlocking); return s; }();
    static cudaEvent_t ev_fork = []{
        cudaEvent_t e; cudaEventCreateWithFlags(&e, cudaEventDisableTiming); return e; }();
    static cudaEvent_t ev_a = []{
        cudaEvent_t e; cudaEventCreateWithFlags(&e, cudaEventDisableTiming); return e; }();
    static cudaEvent_t ev_b = []{
        cudaEvent_t e; cudaEventCreateWithFlags(&e, cudaEventDisableTiming); return e; }();

    // fork: weight transposes on side stream, concurrent with LN1
    cudaEventRecord(ev_fork, 0);
    cudaStreamWaitEvent(s_side, ev_fork, 0);
    transpose4_kernel<<<dim3(EMB/32, EMB/32, 4), 256, 0, s_side>>>(
        Wq, Wk, Wv, Wo, wqkv, wqkv + EMB*EMB, wqkv + 2*EMB*EMB, wo);
    cudaEventRecord(ev_a, s_side);
    transpose_half_kernel<<<dim3(FF/32,  EMB/32), 256, 0, s_side>>>(W1, w1, EMB, FF);
    transpose_half_kernel<<<dim3(EMB/32, FF/32),  256, 0, s_side>>>(W2, w2, FF, EMB);
    cudaEventRecord(ev_b, s_side);

    // main: LN1 concurrent with transpose4
    ln_half_kernel<<<TOK/4, 128>>>(x, ln1s, ln1b, hh);
    cudaStreamWaitEvent(0, ev_a, 0);

    // fused QKV projection -> fp16 (MT=128; Q columns pre-scaled)
    gemm_kernel<3,128,3><<<dim3(QKV_LD/128, TOK/128), 256, GEMM_SMEM_128>>>(
        hh, wqkv, nullptr, nullptr, nullptr, qkv, TOK, QKV_LD, EMB);

    // attention -> ctx fp16
    attn_kernel<<<dim3(SEQ/128, HEADS, BATCH), 256, ATTN_SMEM>>>(qkv, ctx);

    // Wo + bias + residual -> x1 (MT=64, 4-stage)
    gemm_kernel<1,64,4><<<dim3(EMB/128, TOK/64), 256, GEMM_SMEM_64>>>(
        ctx, wo, bo, x, x1, nullptr, TOK, EMB, EMB);

    // LN2 -> h fp16
    ln_half_kernel<<<TOK/4, 128>>>(x1, ln2s, ln2b, hh);

    cudaStreamWaitEvent(0, ev_b, 0);

    // FFN up + GELU -> mid fp16 (MT=128, 3-stage)
    gemm_kernel<2,128,3><<<dim3(FF/128, TOK/128), 256, GEMM_SMEM_128>>>(
        hh, w1, b1, nullptr, nullptr, mid, TOK, FF, EMB);

    // FFN down + bias + residual -> out (MT=64, 4-stage)
    gemm_kernel<1,64,4><<<dim3(EMB/128, TOK/64), 256, GEMM_SMEM_64>>>(
        mid, w2, b2, x1, out, nullptr, TOK, EMB, FF);
}